// round 5
// baseline (speedup 1.0000x reference)
#include <cuda_runtime.h>
#include <cuda_fp16.h>
#include <mma.h>
#include <cstdint>

using namespace nvcuda;

#define B_ 4
#define S_ 2048
#define H_ 1024
#define E_ 8
#define K_ 512
#define F_ 4096

// GEMM tiling (half inputs, fp32 accum): block 256x128x32, 512 threads,
// 16 warps as 4(M) x 4(N), warp tile 64x32.
#define BM 256
#define BN 128
#define BK 32
#define THREADS 512
#define LDA_H 40    // halves; 80B row stride (conflict-free: 20 words mod 32)
#define LDB_H 136   // halves; 272B row stride (conflict-free: 4 words mod 32)
#define LDC 132
#define NSTAGE 3
#define STAGE_HALVES (BM * LDA_H + BK * LDB_H)     // 10240 + 4352 = 14592
#define STAGE_BYTES (STAGE_HALVES * 2)             // 29184
#define SMEM_BYTES (NSTAGE * STAGE_BYTES)          // 87552 (> C chunk 67584)

// ---------------- scratch (device globals: allocation-guard-safe) ----------
__device__ float  g_scores[B_ * E_ * S_];
__device__ int    g_idx[B_ * E_ * K_];
__device__ float  g_gate[B_ * E_ * K_];
__device__ __half g_xgh[(size_t)B_ * E_ * K_ * H_];   // gathered tokens (half)
__device__ __half g_h1h[(size_t)B_ * E_ * K_ * F_];   // hidden (half), 134 MB
__device__ __half g_w1h[(size_t)E_ * H_ * F_];        // W1 as half, [E][H][F]
__device__ __half g_w2h[(size_t)E_ * F_ * H_];        // W2 as half, [E][F][H]

// ---------------- cp.async helpers -----------------------------------------
__device__ __forceinline__ uint32_t smem_u32(const void* p) {
    return (uint32_t)__cvta_generic_to_shared(p);
}
#define CP_ASYNC16(dst_u32, src_ptr) \
    asm volatile("cp.async.cg.shared.global [%0], [%1], 16;\n" :: "r"(dst_u32), "l"(src_ptr))
#define CP_COMMIT() asm volatile("cp.async.commit_group;\n" ::)
#define CP_WAIT1()  asm volatile("cp.async.wait_group 1;\n" ::)

// ---------------- kernel 1: gating + softmax -------------------------------
__global__ __launch_bounds__(256) void gate_kernel(const float* __restrict__ x,
                                                   const float* __restrict__ Wg) {
    int gwarp = (blockIdx.x * blockDim.x + threadIdx.x) >> 5;
    int lane = threadIdx.x & 31;
    if (gwarp >= B_ * S_) return;
    int b = gwarp / S_, s = gwarp % S_;
    const float* xr = x + ((size_t)b * S_ + s) * H_;

    float acc[E_];
#pragma unroll
    for (int e = 0; e < E_; e++) acc[e] = 0.f;
    for (int h = lane; h < H_; h += 32) {
        float xv = xr[h];
#pragma unroll
        for (int e = 0; e < E_; e++) acc[e] += xv * Wg[e * H_ + h];
    }
#pragma unroll
    for (int e = 0; e < E_; e++) {
#pragma unroll
        for (int o = 16; o > 0; o >>= 1)
            acc[e] += __shfl_xor_sync(0xffffffffu, acc[e], o);
    }
    float mx = acc[0];
#pragma unroll
    for (int e = 1; e < E_; e++) mx = fmaxf(mx, acc[e]);
    float den = 0.f;
#pragma unroll
    for (int e = 0; e < E_; e++) den += expf(acc[e] - mx);
    if (lane < E_) {
        g_scores[((size_t)b * E_ + lane) * S_ + s] = expf(acc[lane] - mx) / den;
    }
}

// ---------------- kernel 2: top-K (bitonic, jax.lax.top_k tie order) -------
__device__ __forceinline__ bool precedes(float va, int ia, float vb, int ib) {
    return (va > vb) || (va == vb && ia < ib);
}

__global__ __launch_bounds__(1024) void topk_kernel() {
    __shared__ float sv[S_];
    __shared__ int   si[S_];
    int be = blockIdx.x;
    int tid = threadIdx.x;
    for (int i = tid; i < S_; i += 1024) {
        sv[i] = g_scores[(size_t)be * S_ + i];
        si[i] = i;
    }
    __syncthreads();
    for (int k = 2; k <= S_; k <<= 1) {
        for (int j = k >> 1; j > 0; j >>= 1) {
            for (int i = tid; i < S_; i += 1024) {
                int ixj = i ^ j;
                if (ixj > i) {
                    float va = sv[i], vb = sv[ixj];
                    int ia = si[i], ib = si[ixj];
                    bool up = ((i & k) == 0);
                    bool swp = up ? precedes(vb, ib, va, ia)
                                  : precedes(va, ia, vb, ib);
                    if (swp) {
                        sv[i] = vb; sv[ixj] = va;
                        si[i] = ib; si[ixj] = ia;
                    }
                }
            }
            __syncthreads();
        }
    }
    for (int i = tid; i < K_; i += 1024) {
        g_idx[(size_t)be * K_ + i]  = si[i];
        g_gate[(size_t)be * K_ + i] = sv[i];
    }
}

// ---------------- kernel 2b: gather chosen tokens -> half ------------------
__global__ __launch_bounds__(256) void gather_kernel(const float* __restrict__ x) {
    int row = blockIdx.x;                 // 0..B*E*K-1
    int be = row / K_;
    int b = be / E_;
    int token = g_idx[row];
    const float4* src = (const float4*)(x + ((size_t)b * S_ + token) * H_);
    __half2* dst = (__half2*)(g_xgh + (size_t)row * H_);
    float4 v = src[threadIdx.x];
    dst[threadIdx.x * 2 + 0] = __floats2half2_rn(v.x, v.y);
    dst[threadIdx.x * 2 + 1] = __floats2half2_rn(v.z, v.w);
}

// ---------------- kernel 2c: fp32 -> fp16 convert (layout preserved) -------
__global__ __launch_bounds__(256) void convert_kernel(const float* __restrict__ src,
                                                      __half* __restrict__ dst) {
    size_t i = ((size_t)blockIdx.x * 256 + threadIdx.x) * 4;
    float4 v = *(const float4*)(src + i);
    __half2* d = (__half2*)(dst + i);
    d[0] = __floats2half2_rn(v.x, v.y);
    d[1] = __floats2half2_rn(v.z, v.w);
}

// GELU tanh approximation (JAX default approximate=True)
__device__ __forceinline__ float gelu_tanh(float v) {
    float t = 0.7978845608028654f * (v + 0.044715f * v * v * v);
    return 0.5f * v * (1.f + tanhf(t));
}

// ---------------- shared GEMM mainloop (half WMMA, fp32 accum) -------------
// C[256x128] = A[256 x iters*32] @ B[iters*32 x N](row-major slice at n0)
// 3-stage cp.async ring, 1 syncthreads per iteration.
struct AccTile {
    wmma::fragment<wmma::accumulator, 16, 16, 16, float> a[4][2];
};

__device__ __forceinline__ void gemm_half(const __half* __restrict__ A, size_t lda,
                                          const __half* __restrict__ Bg, size_t ldb,
                                          int n0, int iters, __half* sbase,
                                          AccTile& acc, int tid) {
    const int warp = tid >> 5;
    const int wm = warp >> 2;    // 0..3  (rows wm*64 .. +63)
    const int wn = warp & 3;     // 0..3  (cols wn*32 .. +31)

    auto issue = [&](int j) {
        __half* st = sbase + (j % NSTAGE) * STAGE_HALVES;
        __half* stB = st + BM * LDA_H;
        int k0 = j * BK;
#pragma unroll
        for (int r = 0; r < 2; r++) {
            int g = tid + r * THREADS;       // 0..1023
            int row = g >> 2, c = (g & 3) * 8;
            CP_ASYNC16(smem_u32(st + row * LDA_H + c), A + (size_t)row * lda + k0 + c);
        }
        {
            int row = tid >> 4, c = (tid & 15) * 8;
            CP_ASYNC16(smem_u32(stB + row * LDB_H + c),
                       Bg + (size_t)(k0 + row) * ldb + n0 + c);
        }
    };

    issue(0); CP_COMMIT();
    issue(1); CP_COMMIT();
    for (int j = 0; j < iters; j++) {
        CP_WAIT1();
        __syncthreads();
        if (j + 2 < iters) { issue(j + 2); }
        CP_COMMIT();
        __half* st = sbase + (j % NSTAGE) * STAGE_HALVES;
        __half* stB = st + BM * LDA_H;
#pragma unroll
        for (int kk = 0; kk < BK; kk += 16) {
            wmma::fragment<wmma::matrix_a, 16, 16, 16, __half, wmma::row_major> af[4];
            wmma::fragment<wmma::matrix_b, 16, 16, 16, __half, wmma::row_major> bf[2];
#pragma unroll
            for (int i = 0; i < 4; i++)
                wmma::load_matrix_sync(af[i], st + (wm * 64 + i * 16) * LDA_H + kk, LDA_H);
#pragma unroll
            for (int jj = 0; jj < 2; jj++)
                wmma::load_matrix_sync(bf[jj], stB + kk * LDB_H + wn * 32 + jj * 16, LDB_H);
#pragma unroll
            for (int i = 0; i < 4; i++)
#pragma unroll
                for (int jj = 0; jj < 2; jj++)
                    wmma::mma_sync(acc.a[i][jj], af[i], bf[jj], acc.a[i][jj]);
        }
    }
    __syncthreads();   // all warps done with last stage before smem reuse as C
}

// Store one 128-row chunk (chunk = 0 or 1) of the 256x128 acc into smem C.
__device__ __forceinline__ void store_chunk_smem(float* sC, AccTile& acc,
                                                 int tid, int chunk) {
    const int warp = tid >> 5;
    const int wm = warp >> 2;
    const int wn = warp & 3;
    if ((wm >> 1) == chunk) {
        int lrow = (wm & 1) * 64;
#pragma unroll
        for (int i = 0; i < 4; i++)
#pragma unroll
            for (int j = 0; j < 2; j++)
                wmma::store_matrix_sync(sC + (lrow + i * 16) * LDC + wn * 32 + j * 16,
                                        acc.a[i][j], LDC, wmma::mem_row_major);
    }
}

// ---------------- kernel 3: FFN1 = gelu(Xg @ W1 + b1) -> half --------------
__global__ __launch_bounds__(THREADS, 1) void ffn1_kernel(const float* __restrict__ b1) {
    extern __shared__ __align__(16) __half smem_h[];
    const int tid = threadIdx.x;
    const int e = blockIdx.z, b = blockIdx.y >> 1, mt = blockIdx.y & 1;
    const int n0 = blockIdx.x * BN, m0 = mt * BM;
    const int be = b * E_ + e;

    const __half* A  = g_xgh + ((size_t)be * K_ + m0) * H_;
    const __half* Bg = g_w1h + (size_t)e * H_ * F_;

    AccTile acc;
#pragma unroll
    for (int i = 0; i < 4; i++)
#pragma unroll
        for (int j = 0; j < 2; j++) wmma::fill_fragment(acc.a[i][j], 0.f);

    gemm_half(A, H_, Bg, F_, n0, H_ / BK, smem_h, acc, tid);

    float* sC = (float*)smem_h;
    const float* b1p = b1 + (size_t)e * F_ + n0;
    __half* h1p = g_h1h + ((size_t)be * K_ + m0) * F_ + n0;

#pragma unroll
    for (int chunk = 0; chunk < 2; chunk++) {
        store_chunk_smem(sC, acc, tid, chunk);
        __syncthreads();
#pragma unroll
        for (int r = 0; r < 8; r++) {
            int g = tid + r * THREADS;       // 0..4095 float4s
            int row = g >> 5;
            int col = (g & 31) * 4;
            float4 v = *(const float4*)(sC + row * LDC + col);
            float4 bb = *(const float4*)(b1p + col);
            __half2 h0 = __floats2half2_rn(gelu_tanh(v.x + bb.x), gelu_tanh(v.y + bb.y));
            __half2 h1 = __floats2half2_rn(gelu_tanh(v.z + bb.z), gelu_tanh(v.w + bb.w));
            __half2* dp = (__half2*)(h1p + (size_t)(chunk * 128 + row) * F_ + col);
            dp[0] = h0;
            dp[1] = h1;
        }
        __syncthreads();
    }
}

// ---------------- kernel 4: FFN2 + bias + gate + scatter-add ---------------
__global__ __launch_bounds__(THREADS, 1) void ffn2_kernel(const float* __restrict__ b2,
                                                          float* __restrict__ out) {
    extern __shared__ __align__(16) __half smem_h[];
    const int tid = threadIdx.x;
    const int e = blockIdx.z, b = blockIdx.y >> 1, mt = blockIdx.y & 1;
    const int n0 = blockIdx.x * BN, m0 = mt * BM;
    const int be = b * E_ + e;

    const __half* A  = g_h1h + ((size_t)be * K_ + m0) * F_;
    const __half* Bg = g_w2h + (size_t)e * F_ * H_;

    AccTile acc;
#pragma unroll
    for (int i = 0; i < 4; i++)
#pragma unroll
        for (int j = 0; j < 2; j++) wmma::fill_fragment(acc.a[i][j], 0.f);

    gemm_half(A, F_, Bg, H_, n0, F_ / BK, smem_h, acc, tid);

    float* sC = (float*)smem_h;
    const int*   idxp  = g_idx  + (size_t)be * K_;
    const float* gatep = g_gate + (size_t)be * K_;
    const float* b2p   = b2 + (size_t)e * H_ + n0;

#pragma unroll
    for (int chunk = 0; chunk < 2; chunk++) {
        store_chunk_smem(sC, acc, tid, chunk);
        __syncthreads();
#pragma unroll
        for (int r = 0; r < 8; r++) {
            int g = tid + r * THREADS;
            int row = g >> 5;
            int col = (g & 31) * 4;
            int grow = m0 + chunk * 128 + row;
            float4 v = *(const float4*)(sC + row * LDC + col);
            float4 bb = *(const float4*)(b2p + col);
            float gsc = gatep[grow - m0 + m0];   // g_gate[be][grow]
            gsc = gatep[chunk * 128 + row + mt * 0 + (m0 - m0)];  // simplify below
            gsc = gatep[(m0 + chunk * 128 + row) - m0];
            int token = idxp[(m0 + chunk * 128 + row) - m0];
            // note: idxp/gatep already offset by be*K_, index is absolute row in [0,K)
            token = g_idx[(size_t)be * K_ + m0 + chunk * 128 + row];
            gsc   = g_gate[(size_t)be * K_ + m0 + chunk * 128 + row];
            float* op = out + ((size_t)b * S_ + token) * H_ + n0 + col;
            atomicAdd(op + 0, (v.x + bb.x) * gsc);
            atomicAdd(op + 1, (v.y + bb.y) * gsc);
            atomicAdd(op + 2, (v.z + bb.z) * gsc);
            atomicAdd(op + 3, (v.w + bb.w) * gsc);
        }
        __syncthreads();
    }
}

// ---------------- launch ----------------------------------------------------
extern "C" void kernel_launch(void* const* d_in, const int* in_sizes, int n_in,
                              void* d_out, int out_size) {
    const float* x  = (const float*)d_in[0];
    const float* Wg = (const float*)d_in[1];
    const float* W1 = (const float*)d_in[2];
    const float* b1 = (const float*)d_in[3];
    const float* W2 = (const float*)d_in[4];
    const float* b2 = (const float*)d_in[5];
    float* out = (float*)d_out;

    static int inited = 0;
    if (!inited) {
        cudaFuncSetAttribute(ffn1_kernel, cudaFuncAttributeMaxDynamicSharedMemorySize, SMEM_BYTES);
        cudaFuncSetAttribute(ffn2_kernel, cudaFuncAttributeMaxDynamicSharedMemorySize, SMEM_BYTES);
        inited = 1;
    }

    __half* w1h; cudaGetSymbolAddress((void**)&w1h, g_w1h);
    __half* w2h; cudaGetSymbolAddress((void**)&w2h, g_w2h);

    cudaMemsetAsync(out, 0, (size_t)B_ * S_ * H_ * sizeof(float), 0);
    gate_kernel<<<(B_ * S_) / 8, 256>>>(x, Wg);
    convert_kernel<<<(E_ * (size_t)H_ * F_) / 1024, 256>>>(W1, w1h);
    convert_kernel<<<(E_ * (size_t)F_ * H_) / 1024, 256>>>(W2, w2h);
    topk_kernel<<<B_ * E_, 1024>>>();
    gather_kernel<<<B_ * E_ * K_, 256>>>(x);
    ffn1_kernel<<<dim3(F_ / BN, (B_ * K_) / BM, E_), THREADS, SMEM_BYTES>>>(b1);
    ffn2_kernel<<<dim3(H_ / BN, (B_ * K_) / BM, E_), THREADS, SMEM_BYTES>>>(b2, out);
}

// round 7
// speedup vs baseline: 1.2808x; 1.2808x over previous
#include <cuda_runtime.h>
#include <cuda_fp16.h>
#include <mma.h>
#include <cstdint>

using namespace nvcuda;

#define B_ 4
#define S_ 2048
#define H_ 1024
#define E_ 8
#define K_ 512
#define F_ 4096

// GEMM tiling (half inputs, fp32 accum): block 128x128x32, 256 threads,
// 8 warps as 4(M) x 2(N), warp tile 32x64.
#define BM 128
#define BN 128
#define BK 32
#define LDA_H 40    // halves; 80B row stride
#define LDB_H 136   // halves; 272B row stride
#define LDC 132
#define NSTAGE 4
#define STAGE_HALVES (BM * LDA_H + BK * LDB_H)     // 5120 + 4352 = 9472
#define STAGE_BYTES (STAGE_HALVES * 2)             // 18944
#define SMEM_BYTES (NSTAGE * STAGE_BYTES)          // 75776 (> C tile 67584)

// ---------------- scratch (device globals: allocation-guard-safe) ----------
__device__ float  g_scores[B_ * E_ * S_];
__device__ int    g_idx[B_ * E_ * K_];
__device__ float  g_gate[B_ * E_ * K_];
__device__ __half g_xgh[(size_t)B_ * E_ * K_ * H_];   // gathered tokens (half)
__device__ __half g_h1h[(size_t)B_ * E_ * K_ * F_];   // hidden (half), 134 MB
__device__ __half g_w1h[(size_t)E_ * H_ * F_];        // W1 as half, [E][H][F]
__device__ __half g_w2h[(size_t)E_ * F_ * H_];        // W2 as half, [E][F][H]

// ---------------- cp.async helpers -----------------------------------------
__device__ __forceinline__ uint32_t smem_u32(const void* p) {
    return (uint32_t)__cvta_generic_to_shared(p);
}
#define CP_ASYNC16(dst_u32, src_ptr) \
    asm volatile("cp.async.cg.shared.global [%0], [%1], 16;\n" :: "r"(dst_u32), "l"(src_ptr))
#define CP_COMMIT() asm volatile("cp.async.commit_group;\n" ::)
#define CP_WAIT2()  asm volatile("cp.async.wait_group 2;\n" ::)

// ---------------- kernel 1: gating + softmax -------------------------------
__global__ __launch_bounds__(256) void gate_kernel(const float* __restrict__ x,
                                                   const float* __restrict__ Wg) {
    int gwarp = (blockIdx.x * blockDim.x + threadIdx.x) >> 5;
    int lane = threadIdx.x & 31;
    if (gwarp >= B_ * S_) return;
    int b = gwarp / S_, s = gwarp % S_;
    const float* xr = x + ((size_t)b * S_ + s) * H_;

    float acc[E_];
#pragma unroll
    for (int e = 0; e < E_; e++) acc[e] = 0.f;
    for (int h = lane; h < H_; h += 32) {
        float xv = xr[h];
#pragma unroll
        for (int e = 0; e < E_; e++) acc[e] += xv * Wg[e * H_ + h];
    }
#pragma unroll
    for (int e = 0; e < E_; e++) {
#pragma unroll
        for (int o = 16; o > 0; o >>= 1)
            acc[e] += __shfl_xor_sync(0xffffffffu, acc[e], o);
    }
    float mx = acc[0];
#pragma unroll
    for (int e = 1; e < E_; e++) mx = fmaxf(mx, acc[e]);
    float den = 0.f;
#pragma unroll
    for (int e = 0; e < E_; e++) den += expf(acc[e] - mx);
    if (lane < E_) {
        g_scores[((size_t)b * E_ + lane) * S_ + s] = expf(acc[lane] - mx) / den;
    }
}

// ---------------- kernel 2: top-K (bitonic, jax.lax.top_k tie order) -------
__device__ __forceinline__ bool precedes(float va, int ia, float vb, int ib) {
    return (va > vb) || (va == vb && ia < ib);
}

__global__ __launch_bounds__(1024) void topk_kernel() {
    __shared__ float sv[S_];
    __shared__ int   si[S_];
    int be = blockIdx.x;
    int tid = threadIdx.x;
    for (int i = tid; i < S_; i += 1024) {
        sv[i] = g_scores[(size_t)be * S_ + i];
        si[i] = i;
    }
    __syncthreads();
    for (int k = 2; k <= S_; k <<= 1) {
        for (int j = k >> 1; j > 0; j >>= 1) {
            for (int i = tid; i < S_; i += 1024) {
                int ixj = i ^ j;
                if (ixj > i) {
                    float va = sv[i], vb = sv[ixj];
                    int ia = si[i], ib = si[ixj];
                    bool up = ((i & k) == 0);
                    bool swp = up ? precedes(vb, ib, va, ia)
                                  : precedes(va, ia, vb, ib);
                    if (swp) {
                        sv[i] = vb; sv[ixj] = va;
                        si[i] = ib; si[ixj] = ia;
                    }
                }
            }
            __syncthreads();
        }
    }
    for (int i = tid; i < K_; i += 1024) {
        g_idx[(size_t)be * K_ + i]  = si[i];
        g_gate[(size_t)be * K_ + i] = sv[i];
    }
}

// ---------------- kernel 2b: gather chosen tokens -> half ------------------
__global__ __launch_bounds__(256) void gather_kernel(const float* __restrict__ x) {
    int row = blockIdx.x;                 // 0..B*E*K-1
    int be = row / K_;
    int b = be / E_;
    int token = g_idx[row];
    const float4* src = (const float4*)(x + ((size_t)b * S_ + token) * H_);
    __half2* dst = (__half2*)(g_xgh + (size_t)row * H_);
    float4 v = src[threadIdx.x];
    dst[threadIdx.x * 2 + 0] = __floats2half2_rn(v.x, v.y);
    dst[threadIdx.x * 2 + 1] = __floats2half2_rn(v.z, v.w);
}

// ---------------- kernel 2c: fp32 -> fp16 convert (both weights, one grid) -
#define WELEMS ((size_t)E_ * H_ * F_)
__global__ __launch_bounds__(256) void convert_kernel(const float* __restrict__ w1,
                                                      const float* __restrict__ w2,
                                                      __half* __restrict__ d1,
                                                      __half* __restrict__ d2) {
    size_t i = ((size_t)blockIdx.x * 256 + threadIdx.x) * 4;
    const float* src = w1;
    __half* dst = d1;
    if (i >= WELEMS) { i -= WELEMS; src = w2; dst = d2; }
    float4 v = *(const float4*)(src + i);
    __half2* d = (__half2*)(dst + i);
    d[0] = __floats2half2_rn(v.x, v.y);
    d[1] = __floats2half2_rn(v.z, v.w);
}

// GELU tanh approximation (JAX default approximate=True)
__device__ __forceinline__ float gelu_tanh(float v) {
    float t = 0.7978845608028654f * (v + 0.044715f * v * v * v);
    return 0.5f * v * (1.f + tanhf(t));
}

// ---------------- shared GEMM mainloop (half WMMA, fp32 accum) -------------
// C[128x128] = A[128 x iters*32] @ B[iters*32 x N](row-major slice at n0)
// 4-stage cp.async ring, ONE syncthreads per iteration: the stage written by
// issue(j+3) is (j-1)%4, whose last smem reads (iter j-1) are ordered before
// the top-of-loop barrier of iter j.
struct AccTile {
    wmma::fragment<wmma::accumulator, 16, 16, 16, float> a[2][4];
};

__device__ __forceinline__ void gemm_half(const __half* __restrict__ A, size_t lda,
                                          const __half* __restrict__ Bg, size_t ldb,
                                          int n0, int iters, __half* sbase,
                                          AccTile& acc, int tid) {
    const int warp = tid >> 5;
    const int wm = warp & 3;
    const int wn = warp >> 2;

    auto issue = [&](int j) {
        __half* st = sbase + (j % NSTAGE) * STAGE_HALVES;
        __half* stB = st + BM * LDA_H;
        int k0 = j * BK;
#pragma unroll
        for (int r = 0; r < 2; r++) {
            int g = tid + r * 256;           // 0..511
            int row = g >> 2, c = (g & 3) * 8;
            CP_ASYNC16(smem_u32(st + row * LDA_H + c), A + (size_t)row * lda + k0 + c);
        }
#pragma unroll
        for (int r = 0; r < 2; r++) {
            int g = tid + r * 256;
            int row = g >> 4, c = (g & 15) * 8;
            CP_ASYNC16(smem_u32(stB + row * LDB_H + c),
                       Bg + (size_t)(k0 + row) * ldb + n0 + c);
        }
    };

    issue(0); CP_COMMIT();
    issue(1); CP_COMMIT();
    issue(2); CP_COMMIT();
    for (int j = 0; j < iters; j++) {
        CP_WAIT2();
        __syncthreads();
        if (j + 3 < iters) issue(j + 3);
        CP_COMMIT();
        __half* st = sbase + (j % NSTAGE) * STAGE_HALVES;
        __half* stB = st + BM * LDA_H;
#pragma unroll
        for (int kk = 0; kk < BK; kk += 16) {
            wmma::fragment<wmma::matrix_a, 16, 16, 16, __half, wmma::row_major> af[2];
            wmma::fragment<wmma::matrix_b, 16, 16, 16, __half, wmma::row_major> bf[4];
#pragma unroll
            for (int i = 0; i < 2; i++)
                wmma::load_matrix_sync(af[i], st + (wm * 32 + i * 16) * LDA_H + kk, LDA_H);
#pragma unroll
            for (int jj = 0; jj < 4; jj++)
                wmma::load_matrix_sync(bf[jj], stB + kk * LDB_H + wn * 64 + jj * 16, LDB_H);
#pragma unroll
            for (int i = 0; i < 2; i++)
#pragma unroll
                for (int jj = 0; jj < 4; jj++)
                    wmma::mma_sync(acc.a[i][jj], af[i], bf[jj], acc.a[i][jj]);
        }
    }
    __syncthreads();   // all reads done before smem reuse as C
}

__device__ __forceinline__ void store_acc_smem(float* sC, AccTile& acc, int tid) {
    const int warp = tid >> 5;
    const int wm = warp & 3;
    const int wn = warp >> 2;
#pragma unroll
    for (int i = 0; i < 2; i++)
#pragma unroll
        for (int j = 0; j < 4; j++)
            wmma::store_matrix_sync(sC + (wm * 32 + i * 16) * LDC + wn * 64 + j * 16,
                                    acc.a[i][j], LDC, wmma::mem_row_major);
}

// ---------------- kernel 3: FFN1 = gelu(Xg @ W1 + b1) -> half --------------
__global__ __launch_bounds__(256, 2) void ffn1_kernel(const float* __restrict__ b1) {
    extern __shared__ __align__(16) __half smem_h[];
    const int tid = threadIdx.x;
    const int e = blockIdx.z, b = blockIdx.y >> 2, mt = blockIdx.y & 3;
    const int n0 = blockIdx.x * BN, m0 = mt * BM;
    const int be = b * E_ + e;

    const __half* A  = g_xgh + ((size_t)be * K_ + m0) * H_;
    const __half* Bg = g_w1h + (size_t)e * H_ * F_;

    AccTile acc;
#pragma unroll
    for (int i = 0; i < 2; i++)
#pragma unroll
        for (int j = 0; j < 4; j++) wmma::fill_fragment(acc.a[i][j], 0.f);

    gemm_half(A, H_, Bg, F_, n0, H_ / BK, smem_h, acc, tid);

    float* sC = (float*)smem_h;
    store_acc_smem(sC, acc, tid);
    __syncthreads();

    const float* b1p = b1 + (size_t)e * F_ + n0;
    __half* h1p = g_h1h + ((size_t)be * K_ + m0) * F_ + n0;
#pragma unroll
    for (int r = 0; r < 16; r++) {
        int c = tid + r * 256;
        int row = c >> 5;
        int col = (c & 31) * 4;
        float4 v = *(const float4*)(sC + row * LDC + col);
        float4 bb = *(const float4*)(b1p + col);
        __half2 h0 = __floats2half2_rn(gelu_tanh(v.x + bb.x), gelu_tanh(v.y + bb.y));
        __half2 h1 = __floats2half2_rn(gelu_tanh(v.z + bb.z), gelu_tanh(v.w + bb.w));
        __half2* dp = (__half2*)(h1p + (size_t)row * F_ + col);
        dp[0] = h0;
        dp[1] = h1;
    }
}

// ---------------- kernel 4: FFN2 + bias + gate + scatter-add ---------------
__global__ __launch_bounds__(256, 2) void ffn2_kernel(const float* __restrict__ b2,
                                                      float* __restrict__ out) {
    extern __shared__ __align__(16) __half smem_h[];
    const int tid = threadIdx.x;
    const int e = blockIdx.z, b = blockIdx.y >> 2, mt = blockIdx.y & 3;
    const int n0 = blockIdx.x * BN, m0 = mt * BM;
    const int be = b * E_ + e;

    const __half* A  = g_h1h + ((size_t)be * K_ + m0) * F_;
    const __half* Bg = g_w2h + (size_t)e * F_ * H_;

    AccTile acc;
#pragma unroll
    for (int i = 0; i < 2; i++)
#pragma unroll
        for (int j = 0; j < 4; j++) wmma::fill_fragment(acc.a[i][j], 0.f);

    gemm_half(A, F_, Bg, H_, n0, F_ / BK, smem_h, acc, tid);

    float* sC = (float*)smem_h;
    store_acc_smem(sC, acc, tid);
    __syncthreads();

    const int*   idxp  = g_idx  + (size_t)be * K_ + m0;
    const float* gatep = g_gate + (size_t)be * K_ + m0;
    const float* b2p   = b2 + (size_t)e * H_ + n0;
#pragma unroll
    for (int r = 0; r < 16; r++) {
        int c = tid + r * 256;
        int row = c >> 5;
        int col = (c & 31) * 4;
        float4 v = *(const float4*)(sC + row * LDC + col);
        float4 bb = *(const float4*)(b2p + col);
        float gsc = gatep[row];
        int token = idxp[row];
        float* op = out + ((size_t)b * S_ + token) * H_ + n0 + col;
        atomicAdd(op + 0, (v.x + bb.x) * gsc);
        atomicAdd(op + 1, (v.y + bb.y) * gsc);
        atomicAdd(op + 2, (v.z + bb.z) * gsc);
        atomicAdd(op + 3, (v.w + bb.w) * gsc);
    }
}

// ---------------- launch ----------------------------------------------------
extern "C" void kernel_launch(void* const* d_in, const int* in_sizes, int n_in,
                              void* d_out, int out_size) {
    const float* x  = (const float*)d_in[0];
    const float* Wg = (const float*)d_in[1];
    const float* W1 = (const float*)d_in[2];
    const float* b1 = (const float*)d_in[3];
    const float* W2 = (const float*)d_in[4];
    const float* b2 = (const float*)d_in[5];
    float* out = (float*)d_out;

    cudaFuncSetAttribute(ffn1_kernel, cudaFuncAttributeMaxDynamicSharedMemorySize, SMEM_BYTES);
    cudaFuncSetAttribute(ffn2_kernel, cudaFuncAttributeMaxDynamicSharedMemorySize, SMEM_BYTES);

    __half* w1h; cudaGetSymbolAddress((void**)&w1h, g_w1h);
    __half* w2h; cudaGetSymbolAddress((void**)&w2h, g_w2h);

    cudaMemsetAsync(out, 0, (size_t)B_ * S_ * H_ * sizeof(float), 0);
    gate_kernel<<<(B_ * S_) / 8, 256>>>(x, Wg);
    convert_kernel<<<(int)((2 * WELEMS) / 1024), 256>>>(W1, W2, w1h, w2h);
    topk_kernel<<<B_ * E_, 1024>>>();
    gather_kernel<<<B_ * E_ * K_, 256>>>(x);
    ffn1_kernel<<<dim3(F_ / BN, (B_ * K_) / BM, E_), 256, SMEM_BYTES>>>(b1);
    ffn2_kernel<<<dim3(H_ / BN, (B_ * K_) / BM, E_), 256, SMEM_BYTES>>>(b2, out);
}

// round 8
// speedup vs baseline: 1.3186x; 1.0295x over previous
#include <cuda_runtime.h>
#include <cuda_fp16.h>
#include <mma.h>
#include <cstdint>

using namespace nvcuda;

#define B_ 4
#define S_ 2048
#define H_ 1024
#define E_ 8
#define K_ 512
#define F_ 4096

// GEMM tiling (half inputs, fp32 accum): block 128x128x64, 256 threads,
// 8 warps as 4(M) x 2(N), warp tile 32x64.
#define BM 128
#define BN 128
#define BK 64
#define LDA_H 72    // halves; 144B row stride (36 words: conflict-free ldmatrix)
#define LDB_H 136   // halves; 272B row stride (68 words: conflict-free)
#define LDC 132
#define NSTAGE 3
#define STAGE_HALVES (BM * LDA_H + BK * LDB_H)     // 9216 + 8704 = 17920
#define STAGE_BYTES (STAGE_HALVES * 2)             // 35840
#define SMEM_BYTES (NSTAGE * STAGE_BYTES)          // 107520 (> C tile 67584)

// ---------------- scratch (device globals: allocation-guard-safe) ----------
__device__ float  g_scores[B_ * E_ * S_];
__device__ int    g_idx[B_ * E_ * K_];
__device__ float  g_gate[B_ * E_ * K_];
__device__ __half g_xgh[(size_t)B_ * E_ * K_ * H_];   // gathered tokens (half)
__device__ __half g_h1h[(size_t)B_ * E_ * K_ * F_];   // hidden (half), 134 MB
__device__ __half g_w1h[(size_t)E_ * H_ * F_];        // W1 as half, [E][H][F]
__device__ __half g_w2h[(size_t)E_ * F_ * H_];        // W2 as half, [E][F][H]

// ---------------- cp.async helpers -----------------------------------------
__device__ __forceinline__ uint32_t smem_u32(const void* p) {
    return (uint32_t)__cvta_generic_to_shared(p);
}
#define CP_ASYNC16(dst_u32, src_ptr) \
    asm volatile("cp.async.cg.shared.global [%0], [%1], 16;\n" :: "r"(dst_u32), "l"(src_ptr))
#define CP_COMMIT() asm volatile("cp.async.commit_group;\n" ::)
#define CP_WAIT1()  asm volatile("cp.async.wait_group 1;\n" ::)

// ---------------- kernel 1: gating + softmax -------------------------------
__global__ __launch_bounds__(256) void gate_kernel(const float* __restrict__ x,
                                                   const float* __restrict__ Wg) {
    int gwarp = (blockIdx.x * blockDim.x + threadIdx.x) >> 5;
    int lane = threadIdx.x & 31;
    if (gwarp >= B_ * S_) return;
    int b = gwarp / S_, s = gwarp % S_;
    const float* xr = x + ((size_t)b * S_ + s) * H_;

    float acc[E_];
#pragma unroll
    for (int e = 0; e < E_; e++) acc[e] = 0.f;
    for (int h = lane; h < H_; h += 32) {
        float xv = xr[h];
#pragma unroll
        for (int e = 0; e < E_; e++) acc[e] += xv * Wg[e * H_ + h];
    }
#pragma unroll
    for (int e = 0; e < E_; e++) {
#pragma unroll
        for (int o = 16; o > 0; o >>= 1)
            acc[e] += __shfl_xor_sync(0xffffffffu, acc[e], o);
    }
    float mx = acc[0];
#pragma unroll
    for (int e = 1; e < E_; e++) mx = fmaxf(mx, acc[e]);
    float den = 0.f;
#pragma unroll
    for (int e = 0; e < E_; e++) den += expf(acc[e] - mx);
    if (lane < E_) {
        g_scores[((size_t)b * E_ + lane) * S_ + s] = expf(acc[lane] - mx) / den;
    }
}

// ---------------- kernel 2: top-K (bitonic, jax.lax.top_k tie order) -------
__device__ __forceinline__ bool precedes(float va, int ia, float vb, int ib) {
    return (va > vb) || (va == vb && ia < ib);
}

__global__ __launch_bounds__(1024) void topk_kernel() {
    __shared__ float sv[S_];
    __shared__ int   si[S_];
    int be = blockIdx.x;
    int tid = threadIdx.x;
    for (int i = tid; i < S_; i += 1024) {
        sv[i] = g_scores[(size_t)be * S_ + i];
        si[i] = i;
    }
    __syncthreads();
    for (int k = 2; k <= S_; k <<= 1) {
        for (int j = k >> 1; j > 0; j >>= 1) {
            for (int i = tid; i < S_; i += 1024) {
                int ixj = i ^ j;
                if (ixj > i) {
                    float va = sv[i], vb = sv[ixj];
                    int ia = si[i], ib = si[ixj];
                    bool up = ((i & k) == 0);
                    bool swp = up ? precedes(vb, ib, va, ia)
                                  : precedes(va, ia, vb, ib);
                    if (swp) {
                        sv[i] = vb; sv[ixj] = va;
                        si[i] = ib; si[ixj] = ia;
                    }
                }
            }
            __syncthreads();
        }
    }
    for (int i = tid; i < K_; i += 1024) {
        g_idx[(size_t)be * K_ + i]  = si[i];
        g_gate[(size_t)be * K_ + i] = sv[i];
    }
}

// ---------------- kernel 2b: gather chosen tokens -> half (8 rows/block) ---
__global__ __launch_bounds__(256) void gather_kernel(const float* __restrict__ x) {
    int row = blockIdx.x * 8 + (threadIdx.x >> 5);   // one warp per row
    int lane = threadIdx.x & 31;
    int be = row / K_;
    int b = be / E_;
    int token = g_idx[row];
    const float4* src = (const float4*)(x + ((size_t)b * S_ + token) * H_);
    __half2* dst = (__half2*)(g_xgh + (size_t)row * H_);
#pragma unroll
    for (int i = 0; i < 8; i++) {
        int idx = lane + i * 32;            // 0..255 float4s
        float4 v = src[idx];
        dst[idx * 2 + 0] = __floats2half2_rn(v.x, v.y);
        dst[idx * 2 + 1] = __floats2half2_rn(v.z, v.w);
    }
}

// ---------------- kernel 2c: fp32 -> fp16 convert (both weights, one grid) -
#define WELEMS ((size_t)E_ * H_ * F_)
__global__ __launch_bounds__(256) void convert_kernel(const float* __restrict__ w1,
                                                      const float* __restrict__ w2,
                                                      __half* __restrict__ d1,
                                                      __half* __restrict__ d2) {
    size_t i = ((size_t)blockIdx.x * 256 + threadIdx.x) * 8;
    const float* src = w1;
    __half* dst = d1;
    if (i >= WELEMS) { i -= WELEMS; src = w2; dst = d2; }
    float4 v0 = *(const float4*)(src + i);
    float4 v1 = *(const float4*)(src + i + 4);
    __half2 h[4];
    h[0] = __floats2half2_rn(v0.x, v0.y);
    h[1] = __floats2half2_rn(v0.z, v0.w);
    h[2] = __floats2half2_rn(v1.x, v1.y);
    h[3] = __floats2half2_rn(v1.z, v1.w);
    *(uint4*)(dst + i) = *(uint4*)h;
}

// GELU tanh approximation (JAX default approximate=True)
__device__ __forceinline__ float gelu_tanh(float v) {
    float t = 0.7978845608028654f * (v + 0.044715f * v * v * v);
    return 0.5f * v * (1.f + tanhf(t));
}

// ---------------- shared GEMM mainloop (half WMMA, fp32 accum) -------------
// C[128x128] = A[128 x iters*64] @ B[iters*64 x N](row-major slice at n0)
// 3-stage cp.async ring, one syncthreads per iteration: stage written by
// issue(j+2) is (j-1)%3, whose last smem reads (iter j-1) are ordered before
// the top-of-loop barrier of iter j.
struct AccTile {
    wmma::fragment<wmma::accumulator, 16, 16, 16, float> a[2][4];
};

__device__ __forceinline__ void gemm_half(const __half* __restrict__ A, size_t lda,
                                          const __half* __restrict__ Bg, size_t ldb,
                                          int n0, int iters, __half* sbase,
                                          AccTile& acc, int tid) {
    const int warp = tid >> 5;
    const int wm = warp & 3;
    const int wn = warp >> 2;

    auto issue = [&](int j) {
        __half* st = sbase + (j % NSTAGE) * STAGE_HALVES;
        __half* stB = st + BM * LDA_H;
        int k0 = j * BK;
        // A: 128 rows x 64 halves = 1024 x 16B chunks (8 per row)
#pragma unroll
        for (int r = 0; r < 4; r++) {
            int g = tid + r * 256;
            int row = g >> 3, c = (g & 7) * 8;
            CP_ASYNC16(smem_u32(st + row * LDA_H + c), A + (size_t)row * lda + k0 + c);
        }
        // B: 64 rows x 128 halves = 1024 x 16B chunks (16 per row)
#pragma unroll
        for (int r = 0; r < 4; r++) {
            int g = tid + r * 256;
            int row = g >> 4, c = (g & 15) * 8;
            CP_ASYNC16(smem_u32(stB + row * LDB_H + c),
                       Bg + (size_t)(k0 + row) * ldb + n0 + c);
        }
    };

    issue(0); CP_COMMIT();
    issue(1); CP_COMMIT();
    for (int j = 0; j < iters; j++) {
        CP_WAIT1();
        __syncthreads();
        if (j + 2 < iters) issue(j + 2);
        CP_COMMIT();
        __half* st = sbase + (j % NSTAGE) * STAGE_HALVES;
        __half* stB = st + BM * LDA_H;
#pragma unroll
        for (int kk = 0; kk < BK; kk += 16) {
            wmma::fragment<wmma::matrix_a, 16, 16, 16, __half, wmma::row_major> af[2];
            wmma::fragment<wmma::matrix_b, 16, 16, 16, __half, wmma::row_major> bf[4];
#pragma unroll
            for (int i = 0; i < 2; i++)
                wmma::load_matrix_sync(af[i], st + (wm * 32 + i * 16) * LDA_H + kk, LDA_H);
#pragma unroll
            for (int jj = 0; jj < 4; jj++)
                wmma::load_matrix_sync(bf[jj], stB + kk * LDB_H + wn * 64 + jj * 16, LDB_H);
#pragma unroll
            for (int i = 0; i < 2; i++)
#pragma unroll
                for (int jj = 0; jj < 4; jj++)
                    wmma::mma_sync(acc.a[i][jj], af[i], bf[jj], acc.a[i][jj]);
        }
    }
    __syncthreads();   // all reads done before smem reuse as C
}

__device__ __forceinline__ void store_acc_smem(float* sC, AccTile& acc, int tid) {
    const int warp = tid >> 5;
    const int wm = warp & 3;
    const int wn = warp >> 2;
#pragma unroll
    for (int i = 0; i < 2; i++)
#pragma unroll
        for (int j = 0; j < 4; j++)
            wmma::store_matrix_sync(sC + (wm * 32 + i * 16) * LDC + wn * 64 + j * 16,
                                    acc.a[i][j], LDC, wmma::mem_row_major);
}

// ---------------- kernel 3: FFN1 = gelu(Xg @ W1 + b1) -> half --------------
__global__ __launch_bounds__(256, 2) void ffn1_kernel(const float* __restrict__ b1) {
    extern __shared__ __align__(16) __half smem_h[];
    const int tid = threadIdx.x;
    const int e = blockIdx.z, b = blockIdx.y >> 2, mt = blockIdx.y & 3;
    const int n0 = blockIdx.x * BN, m0 = mt * BM;
    const int be = b * E_ + e;

    const __half* A  = g_xgh + ((size_t)be * K_ + m0) * H_;
    const __half* Bg = g_w1h + (size_t)e * H_ * F_;

    AccTile acc;
#pragma unroll
    for (int i = 0; i < 2; i++)
#pragma unroll
        for (int j = 0; j < 4; j++) wmma::fill_fragment(acc.a[i][j], 0.f);

    gemm_half(A, H_, Bg, F_, n0, H_ / BK, smem_h, acc, tid);

    float* sC = (float*)smem_h;
    store_acc_smem(sC, acc, tid);
    __syncthreads();

    const float* b1p = b1 + (size_t)e * F_ + n0;
    __half* h1p = g_h1h + ((size_t)be * K_ + m0) * F_ + n0;
#pragma unroll
    for (int r = 0; r < 16; r++) {
        int c = tid + r * 256;
        int row = c >> 5;
        int col = (c & 31) * 4;
        float4 v = *(const float4*)(sC + row * LDC + col);
        float4 bb = *(const float4*)(b1p + col);
        __half2 h0 = __floats2half2_rn(gelu_tanh(v.x + bb.x), gelu_tanh(v.y + bb.y));
        __half2 h1 = __floats2half2_rn(gelu_tanh(v.z + bb.z), gelu_tanh(v.w + bb.w));
        __half2* dp = (__half2*)(h1p + (size_t)row * F_ + col);
        dp[0] = h0;
        dp[1] = h1;
    }
}

// ---------------- kernel 4: FFN2 + bias + gate + scatter-add ---------------
__global__ __launch_bounds__(256, 2) void ffn2_kernel(const float* __restrict__ b2,
                                                      float* __restrict__ out) {
    extern __shared__ __align__(16) __half smem_h[];
    const int tid = threadIdx.x;
    const int e = blockIdx.z, b = blockIdx.y >> 2, mt = blockIdx.y & 3;
    const int n0 = blockIdx.x * BN, m0 = mt * BM;
    const int be = b * E_ + e;

    const __half* A  = g_h1h + ((size_t)be * K_ + m0) * F_;
    const __half* Bg = g_w2h + (size_t)e * F_ * H_;

    AccTile acc;
#pragma unroll
    for (int i = 0; i < 2; i++)
#pragma unroll
        for (int j = 0; j < 4; j++) wmma::fill_fragment(acc.a[i][j], 0.f);

    gemm_half(A, F_, Bg, H_, n0, F_ / BK, smem_h, acc, tid);

    float* sC = (float*)smem_h;
    store_acc_smem(sC, acc, tid);
    __syncthreads();

    const int*   idxp  = g_idx  + (size_t)be * K_ + m0;
    const float* gatep = g_gate + (size_t)be * K_ + m0;
    const float* b2p   = b2 + (size_t)e * H_ + n0;
#pragma unroll
    for (int r = 0; r < 16; r++) {
        int c = tid + r * 256;
        int row = c >> 5;
        int col = (c & 31) * 4;
        float4 v = *(const float4*)(sC + row * LDC + col);
        float4 bb = *(const float4*)(b2p + col);
        float gsc = gatep[row];
        int token = idxp[row];
        float* op = out + ((size_t)b * S_ + token) * H_ + n0 + col;
        atomicAdd(op + 0, (v.x + bb.x) * gsc);
        atomicAdd(op + 1, (v.y + bb.y) * gsc);
        atomicAdd(op + 2, (v.z + bb.z) * gsc);
        atomicAdd(op + 3, (v.w + bb.w) * gsc);
    }
}

// ---------------- launch ----------------------------------------------------
extern "C" void kernel_launch(void* const* d_in, const int* in_sizes, int n_in,
                              void* d_out, int out_size) {
    const float* x  = (const float*)d_in[0];
    const float* Wg = (const float*)d_in[1];
    const float* W1 = (const float*)d_in[2];
    const float* b1 = (const float*)d_in[3];
    const float* W2 = (const float*)d_in[4];
    const float* b2 = (const float*)d_in[5];
    float* out = (float*)d_out;

    cudaFuncSetAttribute(ffn1_kernel, cudaFuncAttributeMaxDynamicSharedMemorySize, SMEM_BYTES);
    cudaFuncSetAttribute(ffn2_kernel, cudaFuncAttributeMaxDynamicSharedMemorySize, SMEM_BYTES);

    __half* w1h; cudaGetSymbolAddress((void**)&w1h, g_w1h);
    __half* w2h; cudaGetSymbolAddress((void**)&w2h, g_w2h);

    cudaMemsetAsync(out, 0, (size_t)B_ * S_ * H_ * sizeof(float), 0);
    gate_kernel<<<(B_ * S_) / 8, 256>>>(x, Wg);
    convert_kernel<<<(int)((2 * WELEMS) / 2048), 256>>>(W1, W2, w1h, w2h);
    topk_kernel<<<B_ * E_, 1024>>>();
    gather_kernel<<<(B_ * E_ * K_) / 8, 256>>>(x);
    ffn1_kernel<<<dim3(F_ / BN, (B_ * K_) / BM, E_), 256, SMEM_BYTES>>>(b1);
    ffn2_kernel<<<dim3(H_ / BN, (B_ * K_) / BM, E_), 256, SMEM_BYTES>>>(b2, out);
}

// round 9
// speedup vs baseline: 1.3613x; 1.0324x over previous
#include <cuda_runtime.h>
#include <cuda_fp16.h>
#include <mma.h>
#include <cstdint>

using namespace nvcuda;

#define B_ 4
#define S_ 2048
#define H_ 1024
#define E_ 8
#define K_ 512
#define F_ 4096

// GEMM tiling (half inputs, fp32 accum): block 128x128x64, 256 threads,
// 8 warps as 4(M) x 2(N), warp tile 32x64.
#define BM 128
#define BN 128
#define BK 64
#define LDA_H 72    // halves; 144B row stride (36 words: conflict-free ldmatrix)
#define LDB_H 136   // halves; 272B row stride (68 words: conflict-free)
#define LDC 132
#define NSTAGE 3
#define STAGE_HALVES (BM * LDA_H + BK * LDB_H)     // 9216 + 8704 = 17920
#define STAGE_BYTES (STAGE_HALVES * 2)             // 35840
#define SMEM_BYTES (NSTAGE * STAGE_BYTES)          // 107520 (> C tile 67584)

// ---------------- scratch (device globals: allocation-guard-safe) ----------
__device__ float  g_scores[B_ * E_ * S_];
__device__ int    g_idx[B_ * E_ * K_];
__device__ float  g_gate[B_ * E_ * K_];
__device__ __half g_xgh[(size_t)B_ * E_ * K_ * H_];   // gathered tokens (half)
__device__ __half g_h1h[(size_t)B_ * E_ * K_ * F_];   // hidden (half), 134 MB
__device__ __half g_w1h[(size_t)E_ * H_ * F_];        // W1 as half, [E][H][F]
__device__ __half g_w2h[(size_t)E_ * F_ * H_];        // W2 as half, [E][F][H]

// ---------------- cp.async helpers -----------------------------------------
__device__ __forceinline__ uint32_t smem_u32(const void* p) {
    return (uint32_t)__cvta_generic_to_shared(p);
}
#define CP_ASYNC16(dst_u32, src_ptr) \
    asm volatile("cp.async.cg.shared.global [%0], [%1], 16;\n" :: "r"(dst_u32), "l"(src_ptr))
#define CP_COMMIT() asm volatile("cp.async.commit_group;\n" ::)
#define CP_WAIT1()  asm volatile("cp.async.wait_group 1;\n" ::)

// ---------------- kernel 1: gating + softmax -------------------------------
__global__ __launch_bounds__(256) void gate_kernel(const float* __restrict__ x,
                                                   const float* __restrict__ Wg) {
    int gwarp = (blockIdx.x * blockDim.x + threadIdx.x) >> 5;
    int lane = threadIdx.x & 31;
    if (gwarp >= B_ * S_) return;
    int b = gwarp / S_, s = gwarp % S_;
    const float* xr = x + ((size_t)b * S_ + s) * H_;

    float acc[E_];
#pragma unroll
    for (int e = 0; e < E_; e++) acc[e] = 0.f;
    for (int h = lane; h < H_; h += 32) {
        float xv = xr[h];
#pragma unroll
        for (int e = 0; e < E_; e++) acc[e] += xv * Wg[e * H_ + h];
    }
#pragma unroll
    for (int e = 0; e < E_; e++) {
#pragma unroll
        for (int o = 16; o > 0; o >>= 1)
            acc[e] += __shfl_xor_sync(0xffffffffu, acc[e], o);
    }
    float mx = acc[0];
#pragma unroll
    for (int e = 1; e < E_; e++) mx = fmaxf(mx, acc[e]);
    float den = 0.f;
#pragma unroll
    for (int e = 0; e < E_; e++) den += expf(acc[e] - mx);
    if (lane < E_) {
        g_scores[((size_t)b * E_ + lane) * S_ + s] = expf(acc[lane] - mx) / den;
    }
}

// ---------------- kernel 2: top-K via 4-pass radix select ------------------
// Scores are softmax outputs (positive floats): uint bit order == value order.
// Finds exact threshold T (bits of the K-th largest) via 8-bit radix passes,
// then emits all bits>T plus the first `need` ties. Output order within K is
// irrelevant downstream (FFN rows and scatter-add are order-independent).
__global__ __launch_bounds__(256) void topk_kernel() {
    __shared__ unsigned int hist[256];
    __shared__ unsigned int s_sel, s_need, s_cnt, s_eq;
    int be = blockIdx.x;
    int tid = threadIdx.x;
    const unsigned int* sp = (const unsigned int*)(g_scores + (size_t)be * S_);

    unsigned int bits[8];
    int idxs[8];
#pragma unroll
    for (int j = 0; j < 8; j++) {
        int i = tid + j * 256;
        bits[j] = sp[i];
        idxs[j] = i;
    }
    if (tid == 0) { s_need = K_; s_cnt = 0; s_eq = 0; }

    unsigned int pref = 0, mask = 0;
#pragma unroll
    for (int p = 0; p < 4; p++) {
        int shift = 24 - 8 * p;
        hist[tid] = 0;
        __syncthreads();
#pragma unroll
        for (int j = 0; j < 8; j++) {
            if ((bits[j] & mask) == pref)
                atomicAdd(&hist[(bits[j] >> shift) & 255], 1u);
        }
        __syncthreads();
        if (tid < 32) {
            unsigned int mine[8];
            unsigned int partial = 0;
#pragma unroll
            for (int j = 0; j < 8; j++) {
                mine[j] = hist[255 - (tid * 8 + j)];
                partial += mine[j];
            }
            unsigned int inc = partial;
#pragma unroll
            for (int o = 1; o < 32; o <<= 1) {
                unsigned int v = __shfl_up_sync(0xffffffffu, inc, o);
                if (tid >= o) inc += v;
            }
            unsigned int exc = inc - partial;
            unsigned int need = s_need;
            bool has = (exc < need) && (need <= inc);
            unsigned int bal = __ballot_sync(0xffffffffu, has);
            int src = __ffs(bal) - 1;
            if (tid == src) {
                unsigned int acc = exc;
#pragma unroll
                for (int j = 0; j < 8; j++) {
                    if (acc + mine[j] >= need) {
                        s_sel = 255 - (unsigned int)(tid * 8 + j);
                        s_need = need - acc;
                        break;
                    }
                    acc += mine[j];
                }
            }
        }
        __syncthreads();
        pref |= (s_sel << shift);
        mask |= (0xFFu << shift);
        __syncthreads();
    }

    unsigned int T = pref;
    unsigned int needF = s_need;
#pragma unroll
    for (int j = 0; j < 8; j++) {
        unsigned int bv = bits[j];
        if (bv > T) {
            unsigned int pos = atomicAdd(&s_cnt, 1u);
            g_idx[(size_t)be * K_ + pos]  = idxs[j];
            g_gate[(size_t)be * K_ + pos] = __uint_as_float(bv);
        } else if (bv == T) {
            unsigned int t = atomicAdd(&s_eq, 1u);
            if (t < needF) {
                unsigned int pos = atomicAdd(&s_cnt, 1u);
                g_idx[(size_t)be * K_ + pos]  = idxs[j];
                g_gate[(size_t)be * K_ + pos] = __uint_as_float(bv);
            }
        }
    }
}

// ---------------- kernel 2b: gather chosen tokens -> half (8 rows/block) ---
__global__ __launch_bounds__(256) void gather_kernel(const float* __restrict__ x) {
    int row = blockIdx.x * 8 + (threadIdx.x >> 5);   // one warp per row
    int lane = threadIdx.x & 31;
    int be = row / K_;
    int b = be / E_;
    int token = g_idx[row];
    const float4* src = (const float4*)(x + ((size_t)b * S_ + token) * H_);
    __half2* dst = (__half2*)(g_xgh + (size_t)row * H_);
#pragma unroll
    for (int i = 0; i < 8; i++) {
        int idx = lane + i * 32;            // 0..255 float4s
        float4 v = src[idx];
        dst[idx * 2 + 0] = __floats2half2_rn(v.x, v.y);
        dst[idx * 2 + 1] = __floats2half2_rn(v.z, v.w);
    }
}

// ---------------- kernel 2c: fp32 -> fp16 convert (both weights, one grid) -
#define WELEMS ((size_t)E_ * H_ * F_)
__global__ __launch_bounds__(256) void convert_kernel(const float* __restrict__ w1,
                                                      const float* __restrict__ w2,
                                                      __half* __restrict__ d1,
                                                      __half* __restrict__ d2) {
    size_t i = ((size_t)blockIdx.x * 256 + threadIdx.x) * 8;
    const float* src = w1;
    __half* dst = d1;
    if (i >= WELEMS) { i -= WELEMS; src = w2; dst = d2; }
    float4 v0 = *(const float4*)(src + i);
    float4 v1 = *(const float4*)(src + i + 4);
    __half2 h[4];
    h[0] = __floats2half2_rn(v0.x, v0.y);
    h[1] = __floats2half2_rn(v0.z, v0.w);
    h[2] = __floats2half2_rn(v1.x, v1.y);
    h[3] = __floats2half2_rn(v1.z, v1.w);
    *(uint4*)(dst + i) = *(uint4*)h;
}

// GELU tanh approximation (JAX default approximate=True)
__device__ __forceinline__ float gelu_tanh(float v) {
    float t = 0.7978845608028654f * (v + 0.044715f * v * v * v);
    return 0.5f * v * (1.f + tanhf(t));
}

// ---------------- shared GEMM mainloop (half WMMA, fp32 accum) -------------
// C[128x128] = A[128 x iters*64] @ B[iters*64 x N](row-major slice at n0)
// 3-stage cp.async ring, one syncthreads per iteration: stage written by
// issue(j+2) is (j-1)%3, whose last smem reads (iter j-1) are ordered before
// the top-of-loop barrier of iter j.
struct AccTile {
    wmma::fragment<wmma::accumulator, 16, 16, 16, float> a[2][4];
};

__device__ __forceinline__ void gemm_half(const __half* __restrict__ A, size_t lda,
                                          const __half* __restrict__ Bg, size_t ldb,
                                          int n0, int iters, __half* sbase,
                                          AccTile& acc, int tid) {
    const int warp = tid >> 5;
    const int wm = warp & 3;
    const int wn = warp >> 2;

    auto issue = [&](int j) {
        __half* st = sbase + (j % NSTAGE) * STAGE_HALVES;
        __half* stB = st + BM * LDA_H;
        int k0 = j * BK;
        // A: 128 rows x 64 halves = 1024 x 16B chunks (8 per row)
#pragma unroll
        for (int r = 0; r < 4; r++) {
            int g = tid + r * 256;
            int row = g >> 3, c = (g & 7) * 8;
            CP_ASYNC16(smem_u32(st + row * LDA_H + c), A + (size_t)row * lda + k0 + c);
        }
        // B: 64 rows x 128 halves = 1024 x 16B chunks (16 per row)
#pragma unroll
        for (int r = 0; r < 4; r++) {
            int g = tid + r * 256;
            int row = g >> 4, c = (g & 15) * 8;
            CP_ASYNC16(smem_u32(stB + row * LDB_H + c),
                       Bg + (size_t)(k0 + row) * ldb + n0 + c);
        }
    };

    issue(0); CP_COMMIT();
    issue(1); CP_COMMIT();
    for (int j = 0; j < iters; j++) {
        CP_WAIT1();
        __syncthreads();
        if (j + 2 < iters) issue(j + 2);
        CP_COMMIT();
        __half* st = sbase + (j % NSTAGE) * STAGE_HALVES;
        __half* stB = st + BM * LDA_H;
#pragma unroll
        for (int kk = 0; kk < BK; kk += 16) {
            wmma::fragment<wmma::matrix_a, 16, 16, 16, __half, wmma::row_major> af[2];
            wmma::fragment<wmma::matrix_b, 16, 16, 16, __half, wmma::row_major> bf[4];
#pragma unroll
            for (int i = 0; i < 2; i++)
                wmma::load_matrix_sync(af[i], st + (wm * 32 + i * 16) * LDA_H + kk, LDA_H);
#pragma unroll
            for (int jj = 0; jj < 4; jj++)
                wmma::load_matrix_sync(bf[jj], stB + kk * LDB_H + wn * 64 + jj * 16, LDB_H);
#pragma unroll
            for (int i = 0; i < 2; i++)
#pragma unroll
                for (int jj = 0; jj < 4; jj++)
                    wmma::mma_sync(acc.a[i][jj], af[i], bf[jj], acc.a[i][jj]);
        }
    }
    __syncthreads();   // all reads done before smem reuse as C
}

__device__ __forceinline__ void store_acc_smem(float* sC, AccTile& acc, int tid) {
    const int warp = tid >> 5;
    const int wm = warp & 3;
    const int wn = warp >> 2;
#pragma unroll
    for (int i = 0; i < 2; i++)
#pragma unroll
        for (int j = 0; j < 4; j++)
            wmma::store_matrix_sync(sC + (wm * 32 + i * 16) * LDC + wn * 64 + j * 16,
                                    acc.a[i][j], LDC, wmma::mem_row_major);
}

// ---------------- kernel 3: FFN1 = gelu(Xg @ W1 + b1) -> half --------------
__global__ __launch_bounds__(256, 2) void ffn1_kernel(const float* __restrict__ b1) {
    extern __shared__ __align__(16) __half smem_h[];
    const int tid = threadIdx.x;
    const int e = blockIdx.z, b = blockIdx.y >> 2, mt = blockIdx.y & 3;
    const int n0 = blockIdx.x * BN, m0 = mt * BM;
    const int be = b * E_ + e;

    const __half* A  = g_xgh + ((size_t)be * K_ + m0) * H_;
    const __half* Bg = g_w1h + (size_t)e * H_ * F_;

    AccTile acc;
#pragma unroll
    for (int i = 0; i < 2; i++)
#pragma unroll
        for (int j = 0; j < 4; j++) wmma::fill_fragment(acc.a[i][j], 0.f);

    gemm_half(A, H_, Bg, F_, n0, H_ / BK, smem_h, acc, tid);

    float* sC = (float*)smem_h;
    store_acc_smem(sC, acc, tid);
    __syncthreads();

    const float* b1p = b1 + (size_t)e * F_ + n0;
    __half* h1p = g_h1h + ((size_t)be * K_ + m0) * F_ + n0;
#pragma unroll
    for (int r = 0; r < 16; r++) {
        int c = tid + r * 256;
        int row = c >> 5;
        int col = (c & 31) * 4;
        float4 v = *(const float4*)(sC + row * LDC + col);
        float4 bb = *(const float4*)(b1p + col);
        __half2 h0 = __floats2half2_rn(gelu_tanh(v.x + bb.x), gelu_tanh(v.y + bb.y));
        __half2 h1 = __floats2half2_rn(gelu_tanh(v.z + bb.z), gelu_tanh(v.w + bb.w));
        __half2* dp = (__half2*)(h1p + (size_t)row * F_ + col);
        dp[0] = h0;
        dp[1] = h1;
    }
}

// ---------------- kernel 4: FFN2 + bias + gate + scatter-add ---------------
__global__ __launch_bounds__(256, 2) void ffn2_kernel(const float* __restrict__ b2,
                                                      float* __restrict__ out) {
    extern __shared__ __align__(16) __half smem_h[];
    const int tid = threadIdx.x;
    const int e = blockIdx.z, b = blockIdx.y >> 2, mt = blockIdx.y & 3;
    const int n0 = blockIdx.x * BN, m0 = mt * BM;
    const int be = b * E_ + e;

    const __half* A  = g_h1h + ((size_t)be * K_ + m0) * F_;
    const __half* Bg = g_w2h + (size_t)e * F_ * H_;

    AccTile acc;
#pragma unroll
    for (int i = 0; i < 2; i++)
#pragma unroll
        for (int j = 0; j < 4; j++) wmma::fill_fragment(acc.a[i][j], 0.f);

    gemm_half(A, F_, Bg, H_, n0, F_ / BK, smem_h, acc, tid);

    float* sC = (float*)smem_h;
    store_acc_smem(sC, acc, tid);
    __syncthreads();

    const int*   idxp  = g_idx  + (size_t)be * K_ + m0;
    const float* gatep = g_gate + (size_t)be * K_ + m0;
    const float* b2p   = b2 + (size_t)e * H_ + n0;
#pragma unroll
    for (int r = 0; r < 16; r++) {
        int c = tid + r * 256;
        int row = c >> 5;
        int col = (c & 31) * 4;
        float4 v = *(const float4*)(sC + row * LDC + col);
        float4 bb = *(const float4*)(b2p + col);
        float gsc = gatep[row];
        int token = idxp[row];
        float* op = out + ((size_t)b * S_ + token) * H_ + n0 + col;
        atomicAdd(op + 0, (v.x + bb.x) * gsc);
        atomicAdd(op + 1, (v.y + bb.y) * gsc);
        atomicAdd(op + 2, (v.z + bb.z) * gsc);
        atomicAdd(op + 3, (v.w + bb.w) * gsc);
    }
}

// ---------------- launch ----------------------------------------------------
extern "C" void kernel_launch(void* const* d_in, const int* in_sizes, int n_in,
                              void* d_out, int out_size) {
    const float* x  = (const float*)d_in[0];
    const float* Wg = (const float*)d_in[1];
    const float* W1 = (const float*)d_in[2];
    const float* b1 = (const float*)d_in[3];
    const float* W2 = (const float*)d_in[4];
    const float* b2 = (const float*)d_in[5];
    float* out = (float*)d_out;

    cudaFuncSetAttribute(ffn1_kernel, cudaFuncAttributeMaxDynamicSharedMemorySize, SMEM_BYTES);
    cudaFuncSetAttribute(ffn2_kernel, cudaFuncAttributeMaxDynamicSharedMemorySize, SMEM_BYTES);

    __half* w1h; cudaGetSymbolAddress((void**)&w1h, g_w1h);
    __half* w2h; cudaGetSymbolAddress((void**)&w2h, g_w2h);

    // Order chosen so the ncu -s 5 slot lands on an FFN kernel.
    gate_kernel<<<(B_ * S_) / 8, 256>>>(x, Wg);
    topk_kernel<<<B_ * E_, 256>>>();
    gather_kernel<<<(B_ * E_ * K_) / 8, 256>>>(x);
    convert_kernel<<<(int)((2 * WELEMS) / 2048), 256>>>(W1, W2, w1h, w2h);
    cudaMemsetAsync(out, 0, (size_t)B_ * S_ * H_ * sizeof(float), 0);
    ffn1_kernel<<<dim3(F_ / BN, (B_ * K_) / BM, E_), 256, SMEM_BYTES>>>(b1);
    ffn2_kernel<<<dim3(H_ / BN, (B_ * K_) / BM, E_), 256, SMEM_BYTES>>>(b2, out);
}